// round 15
// baseline (speedup 1.0000x reference)
#include <cuda_runtime.h>
#include <cuda_bf16.h>
#include <cfloat>
#include <math.h>

#define BS 16
#define CAP 64
#define VOCAB 50265
#define TOPK 5
#define SEQ 256
#define AT 32
#define D 768
#define END_ID 2
#define CAND_MAX 1024

// Scratch (allocation-free rule: __device__ globals)
__device__ float g_sce[BS * CAP * D];   // 3.1 MB

// ---------------------------------------------------------------------------
__device__ __forceinline__ float max4(float4 a) {
    return fmaxf(fmaxf(a.x, a.y), fmaxf(a.z, a.w));
}

// small branchy insert — used ONLY on tiny candidate sets
__device__ __forceinline__ void tk_insert(float v, int idx, float lv[5], int li[5]) {
    if (v <= lv[4]) return;
    if (v > lv[2]) {
        if (v > lv[1]) {
            if (v > lv[0]) {
                lv[4]=lv[3]; li[4]=li[3]; lv[3]=lv[2]; li[3]=li[2];
                lv[2]=lv[1]; li[2]=li[1]; lv[1]=lv[0]; li[1]=li[0];
                lv[0]=v; li[0]=idx;
            } else {
                lv[4]=lv[3]; li[4]=li[3]; lv[3]=lv[2]; li[3]=li[2];
                lv[2]=lv[1]; li[2]=li[1]; lv[1]=v; li[1]=idx;
            }
        } else {
            lv[4]=lv[3]; li[4]=li[3]; lv[3]=lv[2]; li[3]=li[2];
            lv[2]=v; li[2]=idx;
        }
    } else {
        if (v > lv[3]) {
            lv[4]=lv[3]; li[4]=li[3]; lv[3]=v; li[3]=idx;
        } else {
            lv[4]=v; li[4]=idx;
        }
    }
}

__device__ __forceinline__ void cand4(float4 x, int idx0, float T,
                                      int* cnt, float* cval, int* cidx) {
    if (x.x >= T) { int p = atomicAdd(cnt, 1); if (p < CAND_MAX) { cval[p] = x.x; cidx[p] = idx0; } }
    if (x.y >= T) { int p = atomicAdd(cnt, 1); if (p < CAND_MAX) { cval[p] = x.y; cidx[p] = idx0 + 1; } }
    if (x.z >= T) { int p = atomicAdd(cnt, 1); if (p < CAND_MAX) { cval[p] = x.z; cidx[p] = idx0 + 2; } }
    if (x.w >= T) { int p = atomicAdd(cnt, 1); if (p < CAND_MAX) { cval[p] = x.w; cidx[p] = idx0 + 3; } }
}

// ---------------------------------------------------------------------------
// Stage 1: one-pass threshold top-5 -> softmax -> weighted embed gather.
// grid = BS*CAP (row per CTA), 256 threads, 4 CTAs/SM (proven R11 config).
// ---------------------------------------------------------------------------
__global__ __launch_bounds__(256, 4)
void topk_sce_kernel(const float* __restrict__ cap_out,
                     const float* __restrict__ emb,
                     float* __restrict__ sce) {
    __shared__ float warm[8 * TOPK];
    __shared__ float Tsh;
    __shared__ int   cnt;
    __shared__ float cval[CAND_MAX];
    __shared__ int   cidx[CAND_MAX];
    __shared__ float wsh[TOPK];
    __shared__ int   ids[TOPK];

    const int t    = threadIdx.x;
    const int lane = t & 31, wid = t >> 5;
    const int row  = blockIdx.x;

    const float* base = cap_out + (size_t)row * VOCAB;
    const int pre   = (4 - (row & 3)) & 3;         // VOCAB%4==1 -> misalign = row%4
    const int n4    = (VOCAB - pre) >> 2;
    const int done  = pre + (n4 << 2);
    const int ntail = VOCAB - done;                // 0..3
    const float4* v4 = (const float4*)(base + pre);

    // ---- warm-up: 2 f4 per thread (first 2048 elements), kept in registers
    float4 w0 = v4[t];
    float4 w1 = v4[t + 256];
    float m = fmaxf(max4(w0), max4(w1));

    // ---- per-warp top-5 of thread maxes (shuffles only) --------------------
    {
        float mv = m;
        #pragma unroll
        for (int r = 0; r < TOPK; r++) {
            float bv = mv; int bl = lane;
            #pragma unroll
            for (int s = 16; s > 0; s >>= 1) {
                float ov = __shfl_xor_sync(0xffffffffu, bv, s);
                int   ol = __shfl_xor_sync(0xffffffffu, bl, s);
                if (ov > bv || (ov == bv && ol < bl)) { bv = ov; bl = ol; }
            }
            if (lane == 0) warm[wid * TOPK + r] = bv;
            if (lane == bl) mv = -FLT_MAX;
        }
    }
    if (t == 0) cnt = 0;
    __syncthreads();

    // ---- warp 0: T = 5th largest of the 40 per-warp winners ----------------
    // Sound: the 5 largest thread-maxes are 5 distinct elements of the sample,
    // so sample-5th >= T, and row-5th >= sample-5th >= T.
    if (wid == 0) {
        float lv[5] = {-FLT_MAX, -FLT_MAX, -FLT_MAX, -FLT_MAX, -FLT_MAX};
        int   li[5] = {0x7fffffff, 0x7fffffff, 0x7fffffff, 0x7fffffff, 0x7fffffff};
        for (int j = lane; j < 8 * TOPK; j += 32) tk_insert(warm[j], j, lv, li);
        int ptr = 0;
        float last = -FLT_MAX;
        #pragma unroll
        for (int r = 0; r < TOPK; r++) {
            float bv = (ptr < 5) ? lv[ptr] : -FLT_MAX;
            int   bi = (ptr < 5) ? li[ptr] : 0x7fffffff;
            #pragma unroll
            for (int s = 16; s > 0; s >>= 1) {
                float ov = __shfl_xor_sync(0xffffffffu, bv, s);
                int   oi = __shfl_xor_sync(0xffffffffu, bi, s);
                if (ov > bv || (ov == bv && oi < bi)) { bv = ov; bi = oi; }
            }
            if (ptr < 5 && li[ptr] == bi && lv[ptr] == bv) ptr++;
            last = bv;
        }
        if (lane == 0) Tsh = last;
    }
    __syncthreads();
    const float T = Tsh;

    // ---- single streaming pass: collect candidates >= T --------------------
    if (max4(w0) >= T) cand4(w0, pre + 4 * t,         T, &cnt, cval, cidx);
    if (max4(w1) >= T) cand4(w1, pre + 4 * (t + 256), T, &cnt, cval, cidx);

    int j = 512 + t;
    for (; j + 768 < n4; j += 1024) {
        float4 a = __ldcs(v4 + j);
        float4 b = __ldcs(v4 + j + 256);
        float4 c = __ldcs(v4 + j + 512);
        float4 d = __ldcs(v4 + j + 768);
        if (max4(a) >= T) cand4(a, pre + 4 * j,         T, &cnt, cval, cidx);
        if (max4(b) >= T) cand4(b, pre + 4 * (j + 256), T, &cnt, cval, cidx);
        if (max4(c) >= T) cand4(c, pre + 4 * (j + 512), T, &cnt, cval, cidx);
        if (max4(d) >= T) cand4(d, pre + 4 * (j + 768), T, &cnt, cval, cidx);
    }
    for (; j < n4; j += 256) {
        float4 a = __ldcs(v4 + j);
        if (max4(a) >= T) cand4(a, pre + 4 * j, T, &cnt, cval, cidx);
    }
    if (t < pre) {
        float v = base[t];
        if (v >= T) { int p = atomicAdd(&cnt, 1); if (p < CAND_MAX) { cval[p] = v; cidx[p] = t; } }
    }
    if (t < ntail) {
        float v = base[done + t];
        if (v >= T) { int p = atomicAdd(&cnt, 1); if (p < CAND_MAX) { cval[p] = v; cidx[p] = done + t; } }
    }
    __syncthreads();

    // ---- exact top-5 of candidates + softmax (warp 0) ----------------------
    if (wid == 0) {
        const int C = (cnt < CAND_MAX) ? cnt : CAND_MAX;
        float lv[5] = {-FLT_MAX, -FLT_MAX, -FLT_MAX, -FLT_MAX, -FLT_MAX};
        int   li[5] = {0x7fffffff, 0x7fffffff, 0x7fffffff, 0x7fffffff, 0x7fffffff};
        for (int q = lane; q < C; q += 32) tk_insert(cval[q], cidx[q], lv, li);

        float tv[TOPK]; int ti[TOPK];
        int ptr = 0;
        #pragma unroll
        for (int r = 0; r < TOPK; r++) {
            float bv = (ptr < 5) ? lv[ptr] : -FLT_MAX;
            int   bi = (ptr < 5) ? li[ptr] : 0x7fffffff;
            #pragma unroll
            for (int s = 16; s > 0; s >>= 1) {
                float ov = __shfl_xor_sync(0xffffffffu, bv, s);
                int   oi = __shfl_xor_sync(0xffffffffu, bi, s);
                if (ov > bv || (ov == bv && oi < bi)) { bv = ov; bi = oi; }
            }
            if (ptr < 5 && li[ptr] == bi && lv[ptr] == bv) ptr++;
            tv[r] = bv; ti[r] = bi;
        }
        if (lane == 0) {
            float mm = tv[0];
            float e0 = expf(tv[0] - mm), e1 = expf(tv[1] - mm), e2 = expf(tv[2] - mm);
            float e3 = expf(tv[3] - mm), e4 = expf(tv[4] - mm);
            float inv5 = 1.0f / (e0 + e1 + e2 + e3 + e4);
            wsh[0]=e0*inv5; wsh[1]=e1*inv5; wsh[2]=e2*inv5; wsh[3]=e3*inv5; wsh[4]=e4*inv5;
            ids[0]=ti[0]; ids[1]=ti[1]; ids[2]=ti[2]; ids[3]=ti[3]; ids[4]=ti[4];
        }
    }
    __syncthreads();

    // ---- weighted embed gather ---------------------------------------------
    const float* e0 = emb + (size_t)ids[0] * D;
    const float* e1 = emb + (size_t)ids[1] * D;
    const float* e2 = emb + (size_t)ids[2] * D;
    const float* e3 = emb + (size_t)ids[3] * D;
    const float* e4 = emb + (size_t)ids[4] * D;
    float w0s = wsh[0], w1s = wsh[1], w2s = wsh[2], w3s = wsh[3], w4s = wsh[4];
    float* srow = sce + (size_t)row * D;
    #pragma unroll
    for (int d = t; d < D; d += 256) {
        srow[d] = w0s*__ldg(e0+d) + w1s*__ldg(e1+d) + w2s*__ldg(e2+d)
                + w3s*__ldg(e3+d) + w4s*__ldg(e4+d);
    }
}

// ---------------------------------------------------------------------------
// Kernel 2: attention with fused scatter — writes its 4 query rows straight
// into the final output at position olen[b]+q (only if q < tlen[b]).
// Fill region rows are disjoint from what assemble writes.
// ---------------------------------------------------------------------------
__global__ __launch_bounds__(256, 4)
void attn_kernel(const float* __restrict__ qin,     // [BS, AT, D]
                 const float* __restrict__ sce,     // [BS, CAP, D]
                 const int*   __restrict__ clen,    // [BS]
                 const int*   __restrict__ olen,    // [BS]
                 const int*   __restrict__ tlen,    // [BS]
                 float*       __restrict__ out) {   // [BS, SEQ, D]
    const int b  = blockIdx.y;
    const int q0 = blockIdx.x * 4;
    const int t  = threadIdx.x;
    const int wid = t >> 5, lane = t & 31;

    __shared__ __align__(16) float qs[4 * D];
    __shared__ float sc[4][CAP];

    const float* qbase = qin + ((size_t)b * AT + q0) * D;
    for (int i = t; i < 4 * D; i += 256) qs[i] = qbase[i];
    __syncthreads();

    {
        const float4* qs4 = (const float4*)qs;
        #pragma unroll
        for (int kk = 0; kk < 8; kk++) {
            const int k = wid * 8 + kk;
            const float4* kr = (const float4*)(sce + ((size_t)b * CAP + k) * D);
            float acc0 = 0.f, acc1 = 0.f, acc2 = 0.f, acc3 = 0.f;
            #pragma unroll
            for (int j = 0; j < D / 128; j++) {
                float4 kv = kr[lane + 32 * j];
                float4 q0v = qs4[0 * (D/4) + lane + 32 * j];
                float4 q1v = qs4[1 * (D/4) + lane + 32 * j];
                float4 q2v = qs4[2 * (D/4) + lane + 32 * j];
                float4 q3v = qs4[3 * (D/4) + lane + 32 * j];
                acc0 += kv.x*q0v.x + kv.y*q0v.y + kv.z*q0v.z + kv.w*q0v.w;
                acc1 += kv.x*q1v.x + kv.y*q1v.y + kv.z*q1v.z + kv.w*q1v.w;
                acc2 += kv.x*q2v.x + kv.y*q2v.y + kv.z*q2v.z + kv.w*q2v.w;
                acc3 += kv.x*q3v.x + kv.y*q3v.y + kv.z*q3v.z + kv.w*q3v.w;
            }
            #pragma unroll
            for (int s = 16; s > 0; s >>= 1) {
                acc0 += __shfl_xor_sync(0xffffffffu, acc0, s);
                acc1 += __shfl_xor_sync(0xffffffffu, acc1, s);
                acc2 += __shfl_xor_sync(0xffffffffu, acc2, s);
                acc3 += __shfl_xor_sync(0xffffffffu, acc3, s);
            }
            if (lane == 0) {
                const float scale = rsqrtf((float)D);
                sc[0][k] = acc0 * scale;
                sc[1][k] = acc1 * scale;
                sc[2][k] = acc2 * scale;
                sc[3][k] = acc3 * scale;
            }
        }
    }
    __syncthreads();

    if (wid < 4) {
        const int cl = clen[b];
        float v0 = (lane      < cl) ? sc[wid][lane]      : -1e9f;
        float v1 = (lane + 32 < cl) ? sc[wid][lane + 32] : -1e9f;
        float m = fmaxf(v0, v1);
        #pragma unroll
        for (int s = 16; s > 0; s >>= 1) m = fmaxf(m, __shfl_xor_sync(0xffffffffu, m, s));
        float x0 = expf(v0 - m), x1 = expf(v1 - m);
        float sum = x0 + x1;
        #pragma unroll
        for (int s = 16; s > 0; s >>= 1) sum += __shfl_xor_sync(0xffffffffu, sum, s);
        float inv = 1.0f / sum;
        sc[wid][lane]      = x0 * inv;
        sc[wid][lane + 32] = x1 * inv;
    }
    __syncthreads();

    float acc[4][3] = {};
    const float* srow = sce + (size_t)b * CAP * D;
    #pragma unroll 4
    for (int k = 0; k < CAP; k++) {
        float r0 = __ldg(srow + (size_t)k * D + t);
        float r1 = __ldg(srow + (size_t)k * D + t + 256);
        float r2 = __ldg(srow + (size_t)k * D + t + 512);
        #pragma unroll
        for (int qi = 0; qi < 4; qi++) {
            float wk = sc[qi][k];
            acc[qi][0] += wk * r0;
            acc[qi][1] += wk * r1;
            acc[qi][2] += wk * r2;
        }
    }
    // Fused scatter: query q0+qi is fill-row rel=q0+qi -> out position olen+rel
    const int ol = __ldg(olen + b);
    const int tl = __ldg(tlen + b);
    #pragma unroll
    for (int qi = 0; qi < 4; qi++) {
        const int rel = q0 + qi;
        if (rel < tl) {                          // olen<128, rel<32 => s<160<SEQ
            float* orow = out + ((size_t)b * SEQ + ol + rel) * D;
            orow[t]       = acc[qi][0];
            orow[t + 256] = acc[qi][1];
            orow[t + 512] = acc[qi][2];
        }
    }
}

// ---------------------------------------------------------------------------
// Kernel 3: default + END rows only (fill rows are attn's). Depends only on
// inputs -> runs on a second stream concurrent with topk.
// ---------------------------------------------------------------------------
__global__ __launch_bounds__(256)
void assemble_kernel(const float* __restrict__ emb,
                     const int*   __restrict__ ids,     // [BS, SEQ]
                     const int*   __restrict__ olen,    // [BS]
                     const int*   __restrict__ tlen,    // [BS]
                     float4*      __restrict__ out) {
    const int i = blockIdx.x * 256 + threadIdx.x;     // over BS*SEQ*(D/8)
    const int total = BS * SEQ * (D / 8);
    if (i >= total) return;
    const int q  = i % (D / 8);                        // pair index within row
    const int bs = i / (D / 8);
    const int s  = bs & (SEQ - 1);
    const int b  = bs >> 8;

    const int rel = s - __ldg(olen + b);
    const int tl  = __ldg(tlen + b);
    if (rel >= 0 && rel < tl) return;                  // attn writes these rows
    const float4* src = (rel == tl)
        ? (const float4*)(emb + (size_t)END_ID * D)
        : (const float4*)(emb + (size_t)__ldg(ids + bs) * D);
    float4 a = src[2 * q];
    float4 c = src[2 * q + 1];
    float4* dst = out + (size_t)bs * (D / 4);
    dst[2 * q]     = a;
    dst[2 * q + 1] = c;
}

// ---------------------------------------------------------------------------
extern "C" void kernel_launch(void* const* d_in, const int* in_sizes, int n_in,
                              void* d_out, int out_size) {
    const float* caption_out      = (const float*)d_in[0];  // [BS,CAP,VOCAB]
    const float* embed_table      = (const float*)d_in[1];  // [VOCAB,D]
    const float* inputs_embeds_at = (const float*)d_in[2];  // [BS,AT,D]
    const int*   input_ids        = (const int*)  d_in[3];  // [BS,SEQ]
    const int*   origin_len       = (const int*)  d_in[4];  // [BS]
    const int*   target_len       = (const int*)  d_in[5];  // [BS]
    const int*   caption_len      = (const int*)  d_in[6];  // [BS]
    float* out = (float*)d_out;

    float* sce; cudaGetSymbolAddress((void**)&sce, g_sce);

    static cudaStream_t s2 = nullptr;
    static cudaEvent_t  e1 = nullptr, e2 = nullptr;
    if (s2 == nullptr) {
        cudaStreamCreateWithFlags(&s2, cudaStreamNonBlocking);
        cudaEventCreateWithFlags(&e1, cudaEventDisableTiming);
        cudaEventCreateWithFlags(&e2, cudaEventDisableTiming);
    }

    // Fork: assemble (input-only deps; writes rows disjoint from attn's)
    cudaEventRecord(e1, 0);
    cudaStreamWaitEvent(s2, e1, 0);
    {
        const int total = BS * SEQ * (D / 8);
        assemble_kernel<<<(total + 255) / 256, 256, 0, s2>>>(
            embed_table, input_ids, origin_len, target_len, (float4*)out);
    }
    cudaEventRecord(e2, s2);

    // Main chain
    topk_sce_kernel<<<BS * CAP, 256>>>(caption_out, embed_table, sce);

    dim3 g2(AT / 4, BS);
    attn_kernel<<<g2, 256>>>(inputs_embeds_at, sce, caption_len,
                             origin_len, target_len, out);

    // Join s2 back into the captured stream
    cudaStreamWaitEvent(0, e2, 0);
}

// round 16
// speedup vs baseline: 1.2788x; 1.2788x over previous
#include <cuda_runtime.h>
#include <cuda_bf16.h>
#include <cfloat>
#include <math.h>

#define BS 16
#define CAP 64
#define VOCAB 50265
#define TOPK 5
#define SEQ 256
#define AT 32
#define D 768
#define END_ID 2
#define CAND_MAX 1024

// Scratch (allocation-free rule: __device__ globals)
__device__ float g_sce[BS * CAP * D];   // 3.1 MB

// ---------------------------------------------------------------------------
__device__ __forceinline__ float max4(float4 a) {
    return fmaxf(fmaxf(a.x, a.y), fmaxf(a.z, a.w));
}

// small branchy insert — used ONLY on tiny candidate sets
__device__ __forceinline__ void tk_insert(float v, int idx, float lv[5], int li[5]) {
    if (v <= lv[4]) return;
    if (v > lv[2]) {
        if (v > lv[1]) {
            if (v > lv[0]) {
                lv[4]=lv[3]; li[4]=li[3]; lv[3]=lv[2]; li[3]=li[2];
                lv[2]=lv[1]; li[2]=li[1]; lv[1]=lv[0]; li[1]=li[0];
                lv[0]=v; li[0]=idx;
            } else {
                lv[4]=lv[3]; li[4]=li[3]; lv[3]=lv[2]; li[3]=li[2];
                lv[2]=lv[1]; li[2]=li[1]; lv[1]=v; li[1]=idx;
            }
        } else {
            lv[4]=lv[3]; li[4]=li[3]; lv[3]=lv[2]; li[3]=li[2];
            lv[2]=v; li[2]=idx;
        }
    } else {
        if (v > lv[3]) {
            lv[4]=lv[3]; li[4]=li[3]; lv[3]=v; li[3]=idx;
        } else {
            lv[4]=v; li[4]=idx;
        }
    }
}

__device__ __forceinline__ void cand4(float4 x, int idx0, float T,
                                      int* cnt, float* cval, int* cidx) {
    if (x.x >= T) { int p = atomicAdd(cnt, 1); if (p < CAND_MAX) { cval[p] = x.x; cidx[p] = idx0; } }
    if (x.y >= T) { int p = atomicAdd(cnt, 1); if (p < CAND_MAX) { cval[p] = x.y; cidx[p] = idx0 + 1; } }
    if (x.z >= T) { int p = atomicAdd(cnt, 1); if (p < CAND_MAX) { cval[p] = x.z; cidx[p] = idx0 + 2; } }
    if (x.w >= T) { int p = atomicAdd(cnt, 1); if (p < CAND_MAX) { cval[p] = x.w; cidx[p] = idx0 + 3; } }
}

// ---------------------------------------------------------------------------
// Stage 1: one-pass threshold top-5 -> softmax -> weighted embed gather.
// grid = BS*CAP (row per CTA), 256 threads, 4 CTAs/SM (proven R11 config).
// ---------------------------------------------------------------------------
__global__ __launch_bounds__(256, 4)
void topk_sce_kernel(const float* __restrict__ cap_out,
                     const float* __restrict__ emb,
                     float* __restrict__ sce) {
    __shared__ float warm[8 * TOPK];
    __shared__ float Tsh;
    __shared__ int   cnt;
    __shared__ float cval[CAND_MAX];
    __shared__ int   cidx[CAND_MAX];
    __shared__ float wsh[TOPK];
    __shared__ int   ids[TOPK];

    const int t    = threadIdx.x;
    const int lane = t & 31, wid = t >> 5;
    const int row  = blockIdx.x;

    const float* base = cap_out + (size_t)row * VOCAB;
    const int pre   = (4 - (row & 3)) & 3;         // VOCAB%4==1 -> misalign = row%4
    const int n4    = (VOCAB - pre) >> 2;
    const int done  = pre + (n4 << 2);
    const int ntail = VOCAB - done;                // 0..3
    const float4* v4 = (const float4*)(base + pre);

    // ---- warm-up: 2 f4 per thread (first 2048 elements), kept in registers
    float4 w0 = v4[t];
    float4 w1 = v4[t + 256];
    float m = fmaxf(max4(w0), max4(w1));

    // ---- per-warp top-5 of thread maxes (shuffles only) --------------------
    {
        float mv = m;
        #pragma unroll
        for (int r = 0; r < TOPK; r++) {
            float bv = mv; int bl = lane;
            #pragma unroll
            for (int s = 16; s > 0; s >>= 1) {
                float ov = __shfl_xor_sync(0xffffffffu, bv, s);
                int   ol = __shfl_xor_sync(0xffffffffu, bl, s);
                if (ov > bv || (ov == bv && ol < bl)) { bv = ov; bl = ol; }
            }
            if (lane == 0) warm[wid * TOPK + r] = bv;
            if (lane == bl) mv = -FLT_MAX;
        }
    }
    if (t == 0) cnt = 0;
    __syncthreads();

    // ---- warp 0: T = 5th largest of the 40 per-warp winners ----------------
    // Sound: the 5 largest thread-maxes are 5 distinct elements of the sample,
    // so sample-5th >= T, and row-5th >= sample-5th >= T.
    if (wid == 0) {
        float lv[5] = {-FLT_MAX, -FLT_MAX, -FLT_MAX, -FLT_MAX, -FLT_MAX};
        int   li[5] = {0x7fffffff, 0x7fffffff, 0x7fffffff, 0x7fffffff, 0x7fffffff};
        for (int j = lane; j < 8 * TOPK; j += 32) tk_insert(warm[j], j, lv, li);
        int ptr = 0;
        float last = -FLT_MAX;
        #pragma unroll
        for (int r = 0; r < TOPK; r++) {
            float bv = (ptr < 5) ? lv[ptr] : -FLT_MAX;
            int   bi = (ptr < 5) ? li[ptr] : 0x7fffffff;
            #pragma unroll
            for (int s = 16; s > 0; s >>= 1) {
                float ov = __shfl_xor_sync(0xffffffffu, bv, s);
                int   oi = __shfl_xor_sync(0xffffffffu, bi, s);
                if (ov > bv || (ov == bv && oi < bi)) { bv = ov; bi = oi; }
            }
            if (ptr < 5 && li[ptr] == bi && lv[ptr] == bv) ptr++;
            last = bv;
        }
        if (lane == 0) Tsh = last;
    }
    __syncthreads();
    const float T = Tsh;

    // ---- single streaming pass: collect candidates >= T --------------------
    if (max4(w0) >= T) cand4(w0, pre + 4 * t,         T, &cnt, cval, cidx);
    if (max4(w1) >= T) cand4(w1, pre + 4 * (t + 256), T, &cnt, cval, cidx);

    int j = 512 + t;
    for (; j + 768 < n4; j += 1024) {
        float4 a = __ldcs(v4 + j);
        float4 b = __ldcs(v4 + j + 256);
        float4 c = __ldcs(v4 + j + 512);
        float4 d = __ldcs(v4 + j + 768);
        if (max4(a) >= T) cand4(a, pre + 4 * j,         T, &cnt, cval, cidx);
        if (max4(b) >= T) cand4(b, pre + 4 * (j + 256), T, &cnt, cval, cidx);
        if (max4(c) >= T) cand4(c, pre + 4 * (j + 512), T, &cnt, cval, cidx);
        if (max4(d) >= T) cand4(d, pre + 4 * (j + 768), T, &cnt, cval, cidx);
    }
    for (; j < n4; j += 256) {
        float4 a = __ldcs(v4 + j);
        if (max4(a) >= T) cand4(a, pre + 4 * j, T, &cnt, cval, cidx);
    }
    if (t < pre) {
        float v = base[t];
        if (v >= T) { int p = atomicAdd(&cnt, 1); if (p < CAND_MAX) { cval[p] = v; cidx[p] = t; } }
    }
    if (t < ntail) {
        float v = base[done + t];
        if (v >= T) { int p = atomicAdd(&cnt, 1); if (p < CAND_MAX) { cval[p] = v; cidx[p] = done + t; } }
    }
    __syncthreads();

    // ---- exact top-5 of candidates + softmax (warp 0) ----------------------
    if (wid == 0) {
        const int C = (cnt < CAND_MAX) ? cnt : CAND_MAX;
        float lv[5] = {-FLT_MAX, -FLT_MAX, -FLT_MAX, -FLT_MAX, -FLT_MAX};
        int   li[5] = {0x7fffffff, 0x7fffffff, 0x7fffffff, 0x7fffffff, 0x7fffffff};
        for (int q = lane; q < C; q += 32) tk_insert(cval[q], cidx[q], lv, li);

        float tv[TOPK]; int ti[TOPK];
        int ptr = 0;
        #pragma unroll
        for (int r = 0; r < TOPK; r++) {
            float bv = (ptr < 5) ? lv[ptr] : -FLT_MAX;
            int   bi = (ptr < 5) ? li[ptr] : 0x7fffffff;
            #pragma unroll
            for (int s = 16; s > 0; s >>= 1) {
                float ov = __shfl_xor_sync(0xffffffffu, bv, s);
                int   oi = __shfl_xor_sync(0xffffffffu, bi, s);
                if (ov > bv || (ov == bv && oi < bi)) { bv = ov; bi = oi; }
            }
            if (ptr < 5 && li[ptr] == bi && lv[ptr] == bv) ptr++;
            tv[r] = bv; ti[r] = bi;
        }
        if (lane == 0) {
            float mm = tv[0];
            float e0 = expf(tv[0] - mm), e1 = expf(tv[1] - mm), e2 = expf(tv[2] - mm);
            float e3 = expf(tv[3] - mm), e4 = expf(tv[4] - mm);
            float inv5 = 1.0f / (e0 + e1 + e2 + e3 + e4);
            wsh[0]=e0*inv5; wsh[1]=e1*inv5; wsh[2]=e2*inv5; wsh[3]=e3*inv5; wsh[4]=e4*inv5;
            ids[0]=ti[0]; ids[1]=ti[1]; ids[2]=ti[2]; ids[3]=ti[3]; ids[4]=ti[4];
        }
    }
    __syncthreads();

    // ---- weighted embed gather ---------------------------------------------
    const float* e0 = emb + (size_t)ids[0] * D;
    const float* e1 = emb + (size_t)ids[1] * D;
    const float* e2 = emb + (size_t)ids[2] * D;
    const float* e3 = emb + (size_t)ids[3] * D;
    const float* e4 = emb + (size_t)ids[4] * D;
    float w0s = wsh[0], w1s = wsh[1], w2s = wsh[2], w3s = wsh[3], w4s = wsh[4];
    float* srow = sce + (size_t)row * D;
    #pragma unroll
    for (int d = t; d < D; d += 256) {
        srow[d] = w0s*__ldg(e0+d) + w1s*__ldg(e1+d) + w2s*__ldg(e2+d)
                + w3s*__ldg(e3+d) + w4s*__ldg(e4+d);
    }
}

// ---------------------------------------------------------------------------
// Kernel 2: attention with fused scatter — writes its 4 query rows straight
// into the final output at position olen[b]+q (only if q < tlen[b]).
// Fill region rows are disjoint from what assemble writes.
// ---------------------------------------------------------------------------
__global__ __launch_bounds__(256, 4)
void attn_kernel(const float* __restrict__ qin,     // [BS, AT, D]
                 const float* __restrict__ sce,     // [BS, CAP, D]
                 const int*   __restrict__ clen,    // [BS]
                 const int*   __restrict__ olen,    // [BS]
                 const int*   __restrict__ tlen,    // [BS]
                 float*       __restrict__ out) {   // [BS, SEQ, D]
    const int b  = blockIdx.y;
    const int q0 = blockIdx.x * 4;
    const int t  = threadIdx.x;
    const int wid = t >> 5, lane = t & 31;

    __shared__ __align__(16) float qs[4 * D];
    __shared__ float sc[4][CAP];

    const float* qbase = qin + ((size_t)b * AT + q0) * D;
    for (int i = t; i < 4 * D; i += 256) qs[i] = qbase[i];
    __syncthreads();

    {
        const float4* qs4 = (const float4*)qs;
        #pragma unroll
        for (int kk = 0; kk < 8; kk++) {
            const int k = wid * 8 + kk;
            const float4* kr = (const float4*)(sce + ((size_t)b * CAP + k) * D);
            float acc0 = 0.f, acc1 = 0.f, acc2 = 0.f, acc3 = 0.f;
            #pragma unroll
            for (int j = 0; j < D / 128; j++) {
                float4 kv = kr[lane + 32 * j];
                float4 q0v = qs4[0 * (D/4) + lane + 32 * j];
                float4 q1v = qs4[1 * (D/4) + lane + 32 * j];
                float4 q2v = qs4[2 * (D/4) + lane + 32 * j];
                float4 q3v = qs4[3 * (D/4) + lane + 32 * j];
                acc0 += kv.x*q0v.x + kv.y*q0v.y + kv.z*q0v.z + kv.w*q0v.w;
                acc1 += kv.x*q1v.x + kv.y*q1v.y + kv.z*q1v.z + kv.w*q1v.w;
                acc2 += kv.x*q2v.x + kv.y*q2v.y + kv.z*q2v.z + kv.w*q2v.w;
                acc3 += kv.x*q3v.x + kv.y*q3v.y + kv.z*q3v.z + kv.w*q3v.w;
            }
            #pragma unroll
            for (int s = 16; s > 0; s >>= 1) {
                acc0 += __shfl_xor_sync(0xffffffffu, acc0, s);
                acc1 += __shfl_xor_sync(0xffffffffu, acc1, s);
                acc2 += __shfl_xor_sync(0xffffffffu, acc2, s);
                acc3 += __shfl_xor_sync(0xffffffffu, acc3, s);
            }
            if (lane == 0) {
                const float scale = rsqrtf((float)D);
                sc[0][k] = acc0 * scale;
                sc[1][k] = acc1 * scale;
                sc[2][k] = acc2 * scale;
                sc[3][k] = acc3 * scale;
            }
        }
    }
    __syncthreads();

    if (wid < 4) {
        const int cl = clen[b];
        float v0 = (lane      < cl) ? sc[wid][lane]      : -1e9f;
        float v1 = (lane + 32 < cl) ? sc[wid][lane + 32] : -1e9f;
        float m = fmaxf(v0, v1);
        #pragma unroll
        for (int s = 16; s > 0; s >>= 1) m = fmaxf(m, __shfl_xor_sync(0xffffffffu, m, s));
        float x0 = expf(v0 - m), x1 = expf(v1 - m);
        float sum = x0 + x1;
        #pragma unroll
        for (int s = 16; s > 0; s >>= 1) sum += __shfl_xor_sync(0xffffffffu, sum, s);
        float inv = 1.0f / sum;
        sc[wid][lane]      = x0 * inv;
        sc[wid][lane + 32] = x1 * inv;
    }
    __syncthreads();

    float acc[4][3] = {};
    const float* srow = sce + (size_t)b * CAP * D;
    #pragma unroll 4
    for (int k = 0; k < CAP; k++) {
        float r0 = __ldg(srow + (size_t)k * D + t);
        float r1 = __ldg(srow + (size_t)k * D + t + 256);
        float r2 = __ldg(srow + (size_t)k * D + t + 512);
        #pragma unroll
        for (int qi = 0; qi < 4; qi++) {
            float wk = sc[qi][k];
            acc[qi][0] += wk * r0;
            acc[qi][1] += wk * r1;
            acc[qi][2] += wk * r2;
        }
    }
    // Fused scatter: query q0+qi is fill-row rel=q0+qi -> out position olen+rel
    const int ol = __ldg(olen + b);
    const int tl = __ldg(tlen + b);
    #pragma unroll
    for (int qi = 0; qi < 4; qi++) {
        const int rel = q0 + qi;
        if (rel < tl) {                          // olen<128, rel<32 => s<160<SEQ
            float* orow = out + ((size_t)b * SEQ + ol + rel) * D;
            orow[t]       = acc[qi][0];
            orow[t + 256] = acc[qi][1];
            orow[t + 512] = acc[qi][2];
        }
    }
}

// ---------------------------------------------------------------------------
// Kernel 3: default + END rows only (fill rows are attn's); serial, stream 0.
// ---------------------------------------------------------------------------
__global__ __launch_bounds__(256)
void assemble_kernel(const float* __restrict__ emb,
                     const int*   __restrict__ ids,     // [BS, SEQ]
                     const int*   __restrict__ olen,    // [BS]
                     const int*   __restrict__ tlen,    // [BS]
                     float4*      __restrict__ out) {
    const int i = blockIdx.x * 256 + threadIdx.x;     // over BS*SEQ*(D/8)
    const int total = BS * SEQ * (D / 8);
    if (i >= total) return;
    const int q  = i % (D / 8);                        // pair index within row
    const int bs = i / (D / 8);
    const int s  = bs & (SEQ - 1);
    const int b  = bs >> 8;

    const int rel = s - __ldg(olen + b);
    const int tl  = __ldg(tlen + b);
    if (rel >= 0 && rel < tl) return;                  // attn wrote these rows
    const float4* src = (rel == tl)
        ? (const float4*)(emb + (size_t)END_ID * D)
        : (const float4*)(emb + (size_t)__ldg(ids + bs) * D);
    float4 a = src[2 * q];
    float4 c = src[2 * q + 1];
    float4* dst = out + (size_t)bs * (D / 4);
    dst[2 * q]     = a;
    dst[2 * q + 1] = c;
}

// ---------------------------------------------------------------------------
extern "C" void kernel_launch(void* const* d_in, const int* in_sizes, int n_in,
                              void* d_out, int out_size) {
    const float* caption_out      = (const float*)d_in[0];  // [BS,CAP,VOCAB]
    const float* embed_table      = (const float*)d_in[1];  // [VOCAB,D]
    const float* inputs_embeds_at = (const float*)d_in[2];  // [BS,AT,D]
    const int*   input_ids        = (const int*)  d_in[3];  // [BS,SEQ]
    const int*   origin_len       = (const int*)  d_in[4];  // [BS]
    const int*   target_len       = (const int*)  d_in[5];  // [BS]
    const int*   caption_len      = (const int*)  d_in[6];  // [BS]
    float* out = (float*)d_out;

    float* sce; cudaGetSymbolAddress((void**)&sce, g_sce);

    topk_sce_kernel<<<BS * CAP, 256>>>(caption_out, embed_table, sce);

    dim3 g2(AT / 4, BS);
    attn_kernel<<<g2, 256>>>(inputs_embeds_at, sce, caption_len,
                             origin_len, target_len, out);

    const int total = BS * SEQ * (D / 8);
    assemble_kernel<<<(total + 255) / 256, 256>>>(embed_table, input_ids,
                                                  origin_len, target_len,
                                                  (float4*)out);
}

// round 17
// speedup vs baseline: 1.6897x; 1.3213x over previous
#include <cuda_runtime.h>
#include <cuda_bf16.h>
#include <cfloat>
#include <math.h>

#define BS 16
#define CAP 64
#define VOCAB 50265
#define TOPK 5
#define SEQ 256
#define AT 32
#define D 768
#define END_ID 2
#define CAND_MAX 1024

#define TOPK_BLOCKS (BS * CAP)                        // 1024
#define ASM_TOTAL   (BS * SEQ * (D / 8))              // 393216
#define ASM_BLOCKS  ((ASM_TOTAL + 255) / 256)         // 1536

// Scratch (allocation-free rule: __device__ globals)
__device__ float g_sce[BS * CAP * D];   // 3.1 MB

// ---------------------------------------------------------------------------
__device__ __forceinline__ float max4(float4 a) {
    return fmaxf(fmaxf(a.x, a.y), fmaxf(a.z, a.w));
}

// small branchy insert — used ONLY on tiny candidate sets
__device__ __forceinline__ void tk_insert(float v, int idx, float lv[5], int li[5]) {
    if (v <= lv[4]) return;
    if (v > lv[2]) {
        if (v > lv[1]) {
            if (v > lv[0]) {
                lv[4]=lv[3]; li[4]=li[3]; lv[3]=lv[2]; li[3]=li[2];
                lv[2]=lv[1]; li[2]=li[1]; lv[1]=lv[0]; li[1]=li[0];
                lv[0]=v; li[0]=idx;
            } else {
                lv[4]=lv[3]; li[4]=li[3]; lv[3]=lv[2]; li[3]=li[2];
                lv[2]=lv[1]; li[2]=li[1]; lv[1]=v; li[1]=idx;
            }
        } else {
            lv[4]=lv[3]; li[4]=li[3]; lv[3]=lv[2]; li[3]=li[2];
            lv[2]=v; li[2]=idx;
        }
    } else {
        if (v > lv[3]) {
            lv[4]=lv[3]; li[4]=li[3]; lv[3]=v; li[3]=idx;
        } else {
            lv[4]=v; li[4]=idx;
        }
    }
}

__device__ __forceinline__ void cand4(float4 x, int idx0, float T,
                                      int* cnt, float* cval, int* cidx) {
    if (x.x >= T) { int p = atomicAdd(cnt, 1); if (p < CAND_MAX) { cval[p] = x.x; cidx[p] = idx0; } }
    if (x.y >= T) { int p = atomicAdd(cnt, 1); if (p < CAND_MAX) { cval[p] = x.y; cidx[p] = idx0 + 1; } }
    if (x.z >= T) { int p = atomicAdd(cnt, 1); if (p < CAND_MAX) { cval[p] = x.z; cidx[p] = idx0 + 2; } }
    if (x.w >= T) { int p = atomicAdd(cnt, 1); if (p < CAND_MAX) { cval[p] = x.w; cidx[p] = idx0 + 3; } }
}

// ---------------------------------------------------------------------------
// Fused kernel: blocks [0,1024) = topk rows; blocks [1024,2560) = assemble.
// Assemble CTAs backfill SM slots while topk warps stall on DRAM latency.
// ---------------------------------------------------------------------------
__global__ __launch_bounds__(256, 4)
void fused_topk_assemble_kernel(const float* __restrict__ cap_out,
                                const float* __restrict__ emb,
                                float* __restrict__ sce,
                                const int*   __restrict__ idsx,   // [BS, SEQ]
                                const int*   __restrict__ olen,   // [BS]
                                const int*   __restrict__ tlen,   // [BS]
                                float4*      __restrict__ out4) {
    // ======================= assemble path ================================
    if (blockIdx.x >= TOPK_BLOCKS) {
        const int i = (blockIdx.x - TOPK_BLOCKS) * 256 + threadIdx.x;
        if (i >= ASM_TOTAL) return;
        const int q  = i % (D / 8);
        const int bs = i / (D / 8);
        const int s  = bs & (SEQ - 1);
        const int b  = bs >> 8;

        const int rel = s - __ldg(olen + b);
        const int tl  = __ldg(tlen + b);
        if (rel >= 0 && rel < tl) return;              // attn writes these rows
        const float4* src = (rel == tl)
            ? (const float4*)(emb + (size_t)END_ID * D)
            : (const float4*)(emb + (size_t)__ldg(idsx + bs) * D);
        float4 a = src[2 * q];
        float4 c = src[2 * q + 1];
        float4* dst = out4 + (size_t)bs * (D / 4);
        dst[2 * q]     = a;
        dst[2 * q + 1] = c;
        return;
    }

    // ======================= topk path ====================================
    __shared__ float warm[8 * TOPK];
    __shared__ float Tsh;
    __shared__ int   cnt;
    __shared__ float cval[CAND_MAX];
    __shared__ int   cidx[CAND_MAX];
    __shared__ float wsh[TOPK];
    __shared__ int   ids[TOPK];

    const int t    = threadIdx.x;
    const int lane = t & 31, wid = t >> 5;
    const int row  = blockIdx.x;

    const float* base = cap_out + (size_t)row * VOCAB;
    const int pre   = (4 - (row & 3)) & 3;         // VOCAB%4==1 -> misalign = row%4
    const int n4    = (VOCAB - pre) >> 2;
    const int done  = pre + (n4 << 2);
    const int ntail = VOCAB - done;                // 0..3
    const float4* v4 = (const float4*)(base + pre);

    // ---- warm-up: 2 f4 per thread (first 2048 elements), kept in registers
    float4 w0 = v4[t];
    float4 w1 = v4[t + 256];
    float m = fmaxf(max4(w0), max4(w1));

    // ---- per-warp top-5 of thread maxes (shuffles only) --------------------
    {
        float mv = m;
        #pragma unroll
        for (int r = 0; r < TOPK; r++) {
            float bv = mv; int bl = lane;
            #pragma unroll
            for (int s = 16; s > 0; s >>= 1) {
                float ov = __shfl_xor_sync(0xffffffffu, bv, s);
                int   ol = __shfl_xor_sync(0xffffffffu, bl, s);
                if (ov > bv || (ov == bv && ol < bl)) { bv = ov; bl = ol; }
            }
            if (lane == 0) warm[wid * TOPK + r] = bv;
            if (lane == bl) mv = -FLT_MAX;
        }
    }
    if (t == 0) cnt = 0;
    __syncthreads();

    // ---- warp 0: T = 5th largest of the 40 per-warp winners ----------------
    // Sound: the 5 largest thread-maxes are 5 distinct elements of the sample,
    // so sample-5th >= T, and row-5th >= sample-5th >= T.
    if (wid == 0) {
        float lv[5] = {-FLT_MAX, -FLT_MAX, -FLT_MAX, -FLT_MAX, -FLT_MAX};
        int   li[5] = {0x7fffffff, 0x7fffffff, 0x7fffffff, 0x7fffffff, 0x7fffffff};
        for (int j = lane; j < 8 * TOPK; j += 32) tk_insert(warm[j], j, lv, li);
        int ptr = 0;
        float last = -FLT_MAX;
        #pragma unroll
        for (int r = 0; r < TOPK; r++) {
            float bv = (ptr < 5) ? lv[ptr] : -FLT_MAX;
            int   bi = (ptr < 5) ? li[ptr] : 0x7fffffff;
            #pragma unroll
            for (int s = 16; s > 0; s >>= 1) {
                float ov = __shfl_xor_sync(0xffffffffu, bv, s);
                int   oi = __shfl_xor_sync(0xffffffffu, bi, s);
                if (ov > bv || (ov == bv && oi < bi)) { bv = ov; bi = oi; }
            }
            if (ptr < 5 && li[ptr] == bi && lv[ptr] == bv) ptr++;
            last = bv;
        }
        if (lane == 0) Tsh = last;
    }
    __syncthreads();
    const float T = Tsh;

    // ---- single streaming pass, 8 loads in flight per thread --------------
    if (max4(w0) >= T) cand4(w0, pre + 4 * t,         T, &cnt, cval, cidx);
    if (max4(w1) >= T) cand4(w1, pre + 4 * (t + 256), T, &cnt, cval, cidx);

    int j = 512 + t;
    for (; j + 1792 < n4; j += 2048) {
        float4 a = __ldcs(v4 + j);
        float4 b = __ldcs(v4 + j + 256);
        float4 c = __ldcs(v4 + j + 512);
        float4 d = __ldcs(v4 + j + 768);
        float4 e = __ldcs(v4 + j + 1024);
        float4 f = __ldcs(v4 + j + 1280);
        float4 g = __ldcs(v4 + j + 1536);
        float4 h = __ldcs(v4 + j + 1792);
        if (max4(a) >= T) cand4(a, pre + 4 * j,          T, &cnt, cval, cidx);
        if (max4(b) >= T) cand4(b, pre + 4 * (j + 256),  T, &cnt, cval, cidx);
        if (max4(c) >= T) cand4(c, pre + 4 * (j + 512),  T, &cnt, cval, cidx);
        if (max4(d) >= T) cand4(d, pre + 4 * (j + 768),  T, &cnt, cval, cidx);
        if (max4(e) >= T) cand4(e, pre + 4 * (j + 1024), T, &cnt, cval, cidx);
        if (max4(f) >= T) cand4(f, pre + 4 * (j + 1280), T, &cnt, cval, cidx);
        if (max4(g) >= T) cand4(g, pre + 4 * (j + 1536), T, &cnt, cval, cidx);
        if (max4(h) >= T) cand4(h, pre + 4 * (j + 1792), T, &cnt, cval, cidx);
    }
    for (; j < n4; j += 256) {
        float4 a = __ldcs(v4 + j);
        if (max4(a) >= T) cand4(a, pre + 4 * j, T, &cnt, cval, cidx);
    }
    if (t < pre) {
        float v = base[t];
        if (v >= T) { int p = atomicAdd(&cnt, 1); if (p < CAND_MAX) { cval[p] = v; cidx[p] = t; } }
    }
    if (t < ntail) {
        float v = base[done + t];
        if (v >= T) { int p = atomicAdd(&cnt, 1); if (p < CAND_MAX) { cval[p] = v; cidx[p] = done + t; } }
    }
    __syncthreads();

    // ---- exact top-5 of candidates + softmax (warp 0) ----------------------
    if (wid == 0) {
        const int C = (cnt < CAND_MAX) ? cnt : CAND_MAX;
        float lv[5] = {-FLT_MAX, -FLT_MAX, -FLT_MAX, -FLT_MAX, -FLT_MAX};
        int   li[5] = {0x7fffffff, 0x7fffffff, 0x7fffffff, 0x7fffffff, 0x7fffffff};
        for (int q = lane; q < C; q += 32) tk_insert(cval[q], cidx[q], lv, li);

        float tv[TOPK]; int ti[TOPK];
        int ptr = 0;
        #pragma unroll
        for (int r = 0; r < TOPK; r++) {
            float bv = (ptr < 5) ? lv[ptr] : -FLT_MAX;
            int   bi = (ptr < 5) ? li[ptr] : 0x7fffffff;
            #pragma unroll
            for (int s = 16; s > 0; s >>= 1) {
                float ov = __shfl_xor_sync(0xffffffffu, bv, s);
                int   oi = __shfl_xor_sync(0xffffffffu, bi, s);
                if (ov > bv || (ov == bv && oi < bi)) { bv = ov; bi = oi; }
            }
            if (ptr < 5 && li[ptr] == bi && lv[ptr] == bv) ptr++;
            tv[r] = bv; ti[r] = bi;
        }
        if (lane == 0) {
            float mm = tv[0];
            float e0 = expf(tv[0] - mm), e1 = expf(tv[1] - mm), e2 = expf(tv[2] - mm);
            float e3 = expf(tv[3] - mm), e4 = expf(tv[4] - mm);
            float inv5 = 1.0f / (e0 + e1 + e2 + e3 + e4);
            wsh[0]=e0*inv5; wsh[1]=e1*inv5; wsh[2]=e2*inv5; wsh[3]=e3*inv5; wsh[4]=e4*inv5;
            ids[0]=ti[0]; ids[1]=ti[1]; ids[2]=ti[2]; ids[3]=ti[3]; ids[4]=ti[4];
        }
    }
    __syncthreads();

    // ---- weighted embed gather ---------------------------------------------
    const float* e0 = emb + (size_t)ids[0] * D;
    const float* e1 = emb + (size_t)ids[1] * D;
    const float* e2 = emb + (size_t)ids[2] * D;
    const float* e3 = emb + (size_t)ids[3] * D;
    const float* e4 = emb + (size_t)ids[4] * D;
    float w0s = wsh[0], w1s = wsh[1], w2s = wsh[2], w3s = wsh[3], w4s = wsh[4];
    float* srow = sce + (size_t)row * D;
    #pragma unroll
    for (int d = t; d < D; d += 256) {
        srow[d] = w0s*__ldg(e0+d) + w1s*__ldg(e1+d) + w2s*__ldg(e2+d)
                + w3s*__ldg(e3+d) + w4s*__ldg(e4+d);
    }
}

// ---------------------------------------------------------------------------
// Kernel 2: attention, 512 threads (16 warps/CTA = 2x latency hiding),
// fused scatter into the final output (fill rows only).
// ---------------------------------------------------------------------------
__global__ __launch_bounds__(512, 2)
void attn_kernel(const float* __restrict__ qin,     // [BS, AT, D]
                 const float* __restrict__ sce,     // [BS, CAP, D]
                 const int*   __restrict__ clen,    // [BS]
                 const int*   __restrict__ olen,    // [BS]
                 const int*   __restrict__ tlen,    // [BS]
                 float*       __restrict__ out) {   // [BS, SEQ, D]
    const int b  = blockIdx.y;
    const int q0 = blockIdx.x * 4;
    const int t  = threadIdx.x;
    const int wid = t >> 5, lane = t & 31;

    __shared__ __align__(16) float qs[4 * D];
    __shared__ float sc[4][CAP];

    const float* qbase = qin + ((size_t)b * AT + q0) * D;
    for (int i = t; i < 4 * D; i += 512) qs[i] = qbase[i];
    __syncthreads();

    // Scores: 16 warps, 4 keys each; lanes stride D (coalesced)
    {
        const float4* qs4 = (const float4*)qs;
        #pragma unroll
        for (int kk = 0; kk < 4; kk++) {
            const int k = wid * 4 + kk;
            const float4* kr = (const float4*)(sce + ((size_t)b * CAP + k) * D);
            float acc0 = 0.f, acc1 = 0.f, acc2 = 0.f, acc3 = 0.f;
            #pragma unroll
            for (int j = 0; j < D / 128; j++) {
                float4 kv = kr[lane + 32 * j];
                float4 q0v = qs4[0 * (D/4) + lane + 32 * j];
                float4 q1v = qs4[1 * (D/4) + lane + 32 * j];
                float4 q2v = qs4[2 * (D/4) + lane + 32 * j];
                float4 q3v = qs4[3 * (D/4) + lane + 32 * j];
                acc0 += kv.x*q0v.x + kv.y*q0v.y + kv.z*q0v.z + kv.w*q0v.w;
                acc1 += kv.x*q1v.x + kv.y*q1v.y + kv.z*q1v.z + kv.w*q1v.w;
                acc2 += kv.x*q2v.x + kv.y*q2v.y + kv.z*q2v.z + kv.w*q2v.w;
                acc3 += kv.x*q3v.x + kv.y*q3v.y + kv.z*q3v.z + kv.w*q3v.w;
            }
            #pragma unroll
            for (int s = 16; s > 0; s >>= 1) {
                acc0 += __shfl_xor_sync(0xffffffffu, acc0, s);
                acc1 += __shfl_xor_sync(0xffffffffu, acc1, s);
                acc2 += __shfl_xor_sync(0xffffffffu, acc2, s);
                acc3 += __shfl_xor_sync(0xffffffffu, acc3, s);
            }
            if (lane == 0) {
                const float scale = rsqrtf((float)D);
                sc[0][k] = acc0 * scale;
                sc[1][k] = acc1 * scale;
                sc[2][k] = acc2 * scale;
                sc[3][k] = acc3 * scale;
            }
        }
    }
    __syncthreads();

    // Masked softmax per query row; warps 0..3 each own one row
    if (wid < 4) {
        const int cl = clen[b];
        float v0 = (lane      < cl) ? sc[wid][lane]      : -1e9f;
        float v1 = (lane + 32 < cl) ? sc[wid][lane + 32] : -1e9f;
        float m = fmaxf(v0, v1);
        #pragma unroll
        for (int s = 16; s > 0; s >>= 1) m = fmaxf(m, __shfl_xor_sync(0xffffffffu, m, s));
        float x0 = expf(v0 - m), x1 = expf(v1 - m);
        float sum = x0 + x1;
        #pragma unroll
        for (int s = 16; s > 0; s >>= 1) sum += __shfl_xor_sync(0xffffffffu, sum, s);
        float inv = 1.0f / sum;
        sc[wid][lane]      = x0 * inv;
        sc[wid][lane + 32] = x1 * inv;
    }
    __syncthreads();

    // Output: thread owns d = t (all 512) and d = t+512 (t < 256 only;
    // warp-uniform predicate since t<256 <=> wid<8)
    const bool lowhalf = (t < 256);
    float acc[4][2] = {};
    const float* srow = sce + (size_t)b * CAP * D;
    #pragma unroll 4
    for (int k = 0; k < CAP; k++) {
        float r0 = __ldg(srow + (size_t)k * D + t);
        float r1 = lowhalf ? __ldg(srow + (size_t)k * D + t + 512) : 0.0f;
        #pragma unroll
        for (int qi = 0; qi < 4; qi++) {
            float wk = sc[qi][k];
            acc[qi][0] += wk * r0;
            acc[qi][1] += wk * r1;
        }
    }
    // Fused scatter: query q0+qi -> out position olen+rel (rel < tlen only)
    const int ol = __ldg(olen + b);
    const int tl = __ldg(tlen + b);
    #pragma unroll
    for (int qi = 0; qi < 4; qi++) {
        const int rel = q0 + qi;
        if (rel < tl) {                          // olen<128, rel<32 => s<160<SEQ
            float* orow = out + ((size_t)b * SEQ + ol + rel) * D;
            orow[t] = acc[qi][0];
            if (lowhalf) orow[t + 512] = acc[qi][1];
        }
    }
}

// ---------------------------------------------------------------------------
extern "C" void kernel_launch(void* const* d_in, const int* in_sizes, int n_in,
                              void* d_out, int out_size) {
    const float* caption_out      = (const float*)d_in[0];  // [BS,CAP,VOCAB]
    const float* embed_table      = (const float*)d_in[1];  // [VOCAB,D]
    const float* inputs_embeds_at = (const float*)d_in[2];  // [BS,AT,D]
    const int*   input_ids        = (const int*)  d_in[3];  // [BS,SEQ]
    const int*   origin_len       = (const int*)  d_in[4];  // [BS]
    const int*   target_len       = (const int*)  d_in[5];  // [BS]
    const int*   caption_len      = (const int*)  d_in[6];  // [BS]
    float* out = (float*)d_out;

    float* sce; cudaGetSymbolAddress((void**)&sce, g_sce);

    fused_topk_assemble_kernel<<<TOPK_BLOCKS + ASM_BLOCKS, 256>>>(
        caption_out, embed_table, sce,
        input_ids, origin_len, target_len, (float4*)out);

    dim3 g2(AT / 4, BS);
    attn_kernel<<<g2, 512>>>(inputs_embeds_at, sce, caption_len,
                             origin_len, target_len, out);
}